// round 1
// baseline (speedup 1.0000x reference)
#include <cuda_runtime.h>

// Problem constants
#define Bb    8
#define Tseq  2048
#define Cdim  1024
#define Hdim  64
#define BT    (Bb * Tseq)
#define SCALE 0.125f   // 64^-0.5

// Scratch for projections (device globals — no allocation allowed)
__device__ float g_q[BT * Hdim];
__device__ float g_k[BT * Hdim];
__device__ float g_v[BT * Hdim];

// ---------------------------------------------------------------------------
// Kernel 1: fused projection GEMM.  q/k/v = x @ w{q,k,v}
// M = BT = 16384, K = 1024, N = 64.  BM=64, BK=32, N covered by one tile.
// 256 threads as 16x16, each computing a 4x4 micro-tile per output matrix.
// ---------------------------------------------------------------------------
__global__ __launch_bounds__(256) void proj_kernel(
    const float* __restrict__ x,
    const float* __restrict__ wq,
    const float* __restrict__ wk,
    const float* __restrict__ wv)
{
    __shared__ float xs [64][36];   // 36*4 = 144B rows: 16B aligned for float4 stores
    __shared__ float wqs[32][68];   // 68*4 = 272B rows: 16B aligned
    __shared__ float wks[32][68];
    __shared__ float wvs[32][68];

    const int tid  = threadIdx.x;
    const int tx   = tid & 15;      // 0..15 -> 4 output cols each
    const int ty   = tid >> 4;      // 0..15 -> 4 output rows each
    const int row0 = blockIdx.x * 64;

    float accq[4][4] = {};
    float acck[4][4] = {};
    float accv[4][4] = {};

    for (int k0 = 0; k0 < Cdim; k0 += 32) {
        // x tile: 64x32 floats = 512 float4, 2 per thread (coalesced)
        #pragma unroll
        for (int t = 0; t < 2; t++) {
            int idx = tid + t * 256;           // 0..511
            int r   = idx >> 3;                // row 0..63
            int c4  = idx & 7;                 // float4 col 0..7
            float4 v = *(const float4*)&x[(size_t)(row0 + r) * Cdim + k0 + c4 * 4];
            *(float4*)&xs[r][c4 * 4] = v;
        }
        // w tiles: 32x64 floats each = 512 float4, 2 per thread per matrix
        #pragma unroll
        for (int t = 0; t < 2; t++) {
            int idx = tid + t * 256;
            int r   = idx >> 4;                // k row 0..31
            int c4  = idx & 15;                // float4 col 0..15
            size_t go = (size_t)(k0 + r) * Hdim + c4 * 4;
            *(float4*)&wqs[r][c4 * 4] = *(const float4*)&wq[go];
            *(float4*)&wks[r][c4 * 4] = *(const float4*)&wk[go];
            *(float4*)&wvs[r][c4 * 4] = *(const float4*)&wv[go];
        }
        __syncthreads();

        #pragma unroll
        for (int kk = 0; kk < 32; kk++) {
            float xa[4];
            #pragma unroll
            for (int i = 0; i < 4; i++) xa[i] = xs[ty * 4 + i][kk];  // broadcast
            float4 bq = *(const float4*)&wqs[kk][tx * 4];             // LDS.128, conflict-free
            float4 bk = *(const float4*)&wks[kk][tx * 4];
            float4 bv = *(const float4*)&wvs[kk][tx * 4];
            #pragma unroll
            for (int i = 0; i < 4; i++) {
                accq[i][0] += xa[i] * bq.x;  accq[i][1] += xa[i] * bq.y;
                accq[i][2] += xa[i] * bq.z;  accq[i][3] += xa[i] * bq.w;
                acck[i][0] += xa[i] * bk.x;  acck[i][1] += xa[i] * bk.y;
                acck[i][2] += xa[i] * bk.z;  acck[i][3] += xa[i] * bk.w;
                accv[i][0] += xa[i] * bv.x;  accv[i][1] += xa[i] * bv.y;
                accv[i][2] += xa[i] * bv.z;  accv[i][3] += xa[i] * bv.w;
            }
        }
        __syncthreads();
    }

    #pragma unroll
    for (int i = 0; i < 4; i++) {
        size_t o = (size_t)(row0 + ty * 4 + i) * Hdim + tx * 4;
        *(float4*)&g_q[o] = make_float4(accq[i][0], accq[i][1], accq[i][2], accq[i][3]);
        *(float4*)&g_k[o] = make_float4(acck[i][0], acck[i][1], acck[i][2], acck[i][3]);
        *(float4*)&g_v[o] = make_float4(accv[i][0], accv[i][1], accv[i][2], accv[i][3]);
    }
}

// ---------------------------------------------------------------------------
// Kernel 2: flash attention (causal, online softmax).
// grid = (T/64, B); 256 threads as 16x16; each thread owns a 4x4 tile of
// S (64 q x 64 k) and of O (64 q x 64 h). Row statistics reduced across the
// 16 tx lanes of each half-warp via shfl (width 16).
// ---------------------------------------------------------------------------
#define PADW 68
#define ATTN_SMEM (4 * 64 * PADW * (int)sizeof(float))   // 69632 bytes

__global__ __launch_bounds__(256) void attn_kernel(float* __restrict__ out)
{
    extern __shared__ float sm[];
    float (*qsT)[PADW] = (float(*)[PADW])(sm);                 // [d][qrow], pre-scaled
    float (*ksT)[PADW] = (float(*)[PADW])(sm + 64 * PADW);     // [d][krow]
    float (*vs )[PADW] = (float(*)[PADW])(sm + 2 * 64 * PADW); // [krow][h]
    float (*ps )[PADW] = (float(*)[PADW])(sm + 3 * 64 * PADW); // [qrow][kcol]

    const int tid = threadIdx.x;
    const int tx  = tid & 15;
    const int ty  = tid >> 4;
    const int q0  = blockIdx.x * 64;
    const int b   = blockIdx.y;

    const float* qg = g_q + (size_t)b * Tseq * Hdim;
    const float* kg = g_k + (size_t)b * Tseq * Hdim;
    const float* vg = g_v + (size_t)b * Tseq * Hdim;

    // Load Q tile (64x64) transposed into qsT, scaled. 1024 float4, 4/thread.
    #pragma unroll
    for (int t = 0; t < 4; t++) {
        int idx = tid + t * 256;           // 0..1023
        int r   = idx >> 4;                // q row 0..63
        int h4  = idx & 15;
        float4 v = *(const float4*)&qg[(size_t)(q0 + r) * Hdim + h4 * 4];
        qsT[h4 * 4 + 0][r] = v.x * SCALE;
        qsT[h4 * 4 + 1][r] = v.y * SCALE;
        qsT[h4 * 4 + 2][r] = v.z * SCALE;
        qsT[h4 * 4 + 3][r] = v.w * SCALE;
    }

    float m[4], l[4], O[4][4];
    #pragma unroll
    for (int i = 0; i < 4; i++) {
        m[i] = -1e30f; l[i] = 0.f;
        #pragma unroll
        for (int j = 0; j < 4; j++) O[i][j] = 0.f;
    }

    const int ntiles = q0 / 64 + 1;
    for (int kt = 0; kt < ntiles; kt++) {
        const int k0 = kt * 64;
        __syncthreads();   // prior PV done (and Q load on first iter) before overwrite

        // Load K (transposed) and V tiles
        #pragma unroll
        for (int t = 0; t < 4; t++) {
            int idx = tid + t * 256;
            int r   = idx >> 4;
            int h4  = idx & 15;
            float4 kv = *(const float4*)&kg[(size_t)(k0 + r) * Hdim + h4 * 4];
            ksT[h4 * 4 + 0][r] = kv.x;
            ksT[h4 * 4 + 1][r] = kv.y;
            ksT[h4 * 4 + 2][r] = kv.z;
            ksT[h4 * 4 + 3][r] = kv.w;
            *(float4*)&vs[r][h4 * 4] = *(const float4*)&vg[(size_t)(k0 + r) * Hdim + h4 * 4];
        }
        __syncthreads();

        // S = Q K^T  (4x4 per thread)
        float S[4][4] = {};
        #pragma unroll
        for (int d = 0; d < 64; d++) {
            float4 qa = *(const float4*)&qsT[d][ty * 4];
            float4 kb = *(const float4*)&ksT[d][tx * 4];
            float qv[4] = {qa.x, qa.y, qa.z, qa.w};
            float kv[4] = {kb.x, kb.y, kb.z, kb.w};
            #pragma unroll
            for (int i = 0; i < 4; i++)
                #pragma unroll
                for (int j = 0; j < 4; j++)
                    S[i][j] += qv[i] * kv[j];
        }

        // Causal mask (only the diagonal tile needs it)
        if (k0 == q0) {
            #pragma unroll
            for (int i = 0; i < 4; i++)
                #pragma unroll
                for (int j = 0; j < 4; j++)
                    if (k0 + tx * 4 + j > q0 + ty * 4 + i) S[i][j] = -1e30f;
        }

        // Online softmax per q-row; reductions across the 16 tx lanes (width-16 shfl)
        #pragma unroll
        for (int i = 0; i < 4; i++) {
            float mloc = fmaxf(fmaxf(S[i][0], S[i][1]), fmaxf(S[i][2], S[i][3]));
            #pragma unroll
            for (int off = 8; off >= 1; off >>= 1)
                mloc = fmaxf(mloc, __shfl_xor_sync(0xffffffffu, mloc, off, 16));
            float mnew  = fmaxf(m[i], mloc);
            float alpha = __expf(m[i] - mnew);
            float lloc = 0.f;
            #pragma unroll
            for (int j = 0; j < 4; j++) {
                S[i][j] = __expf(S[i][j] - mnew);
                lloc += S[i][j];
            }
            #pragma unroll
            for (int off = 8; off >= 1; off >>= 1)
                lloc += __shfl_xor_sync(0xffffffffu, lloc, off, 16);
            l[i] = l[i] * alpha + lloc;
            m[i] = mnew;
            #pragma unroll
            for (int j = 0; j < 4; j++) O[i][j] *= alpha;
        }

        // P -> smem
        #pragma unroll
        for (int i = 0; i < 4; i++)
            *(float4*)&ps[ty * 4 + i][tx * 4] = make_float4(S[i][0], S[i][1], S[i][2], S[i][3]);
        __syncthreads();

        // O += P V
        #pragma unroll
        for (int c = 0; c < 64; c++) {
            float pa[4];
            #pragma unroll
            for (int i = 0; i < 4; i++) pa[i] = ps[ty * 4 + i][c];  // broadcast
            float4 vb = *(const float4*)&vs[c][tx * 4];              // LDS.128, conflict-free
            float vv[4] = {vb.x, vb.y, vb.z, vb.w};
            #pragma unroll
            for (int i = 0; i < 4; i++)
                #pragma unroll
                for (int j = 0; j < 4; j++)
                    O[i][j] += pa[i] * vv[j];
        }
    }

    // Epilogue: normalize and store
    #pragma unroll
    for (int i = 0; i < 4; i++) {
        float inv = 1.0f / l[i];
        size_t o = ((size_t)b * Tseq + q0 + ty * 4 + i) * Hdim + tx * 4;
        *(float4*)&out[o] = make_float4(O[i][0] * inv, O[i][1] * inv,
                                        O[i][2] * inv, O[i][3] * inv);
    }
}

// ---------------------------------------------------------------------------
extern "C" void kernel_launch(void* const* d_in, const int* in_sizes, int n_in,
                              void* d_out, int out_size)
{
    const float* x  = (const float*)d_in[0];
    const float* wq = (const float*)d_in[1];
    const float* wk = (const float*)d_in[2];
    const float* wv = (const float*)d_in[3];
    float* out = (float*)d_out;

    cudaFuncSetAttribute(attn_kernel, cudaFuncAttributeMaxDynamicSharedMemorySize,
                         ATTN_SMEM);

    proj_kernel<<<BT / 64, 256>>>(x, wq, wk, wv);
    attn_kernel<<<dim3(Tseq / 64, Bb), 256, ATTN_SMEM>>>(out);
}

// round 3
// speedup vs baseline: 1.2068x; 1.2068x over previous
#include <cuda_runtime.h>
#include <cuda_bf16.h>
#include <cstdint>

// Problem constants
#define Bb    8
#define Tseq  2048
#define Cdim  1024
#define Hdim  64
#define BT    (Bb * Tseq)
#define SCALE 0.125f   // 64^-0.5

// Scratch (device globals — no allocation allowed)
__device__ float g_q[BT * Hdim];
__device__ float g_k[BT * Hdim];
__device__ float g_v[BT * Hdim];
__device__ __nv_bfloat16 g_xh[BT * Cdim];
__device__ __nv_bfloat16 g_xl[BT * Cdim];
__device__ __nv_bfloat16 g_bh[192 * Cdim];   // packed [wq|wk|wv]^T, row n: B[n][k]
__device__ __nv_bfloat16 g_bl[192 * Cdim];

// ===========================================================================
// Generic-PTX tensor helpers (sm_80+ ISA: works under compute_103 target)
// ===========================================================================
#define CP_ASYNC16(smem_u32, gptr) \
    asm volatile("cp.async.cg.shared.global [%0], [%1], 16;" \
                 :: "r"(smem_u32), "l"(gptr) : "memory")
#define CP_COMMIT() asm volatile("cp.async.commit_group;" ::: "memory")
#define CP_WAIT(N)  asm volatile("cp.async.wait_group %0;" :: "n"(N) : "memory")

#define LDMATRIX_X4(r0, r1, r2, r3, addr) \
    asm volatile("ldmatrix.sync.aligned.m8n8.x4.shared.b16 {%0,%1,%2,%3}, [%4];" \
                 : "=r"(r0), "=r"(r1), "=r"(r2), "=r"(r3) : "r"(addr))

#define MMA_BF16(d, a, b0, b1) \
    asm volatile("mma.sync.aligned.m16n8k16.row.col.f32.bf16.bf16.f32 " \
                 "{%0,%1,%2,%3}, {%4,%5,%6,%7}, {%8,%9}, {%0,%1,%2,%3};" \
                 : "+f"((d)[0]), "+f"((d)[1]), "+f"((d)[2]), "+f"((d)[3]) \
                 : "r"((a)[0]), "r"((a)[1]), "r"((a)[2]), "r"((a)[3]), \
                   "r"(b0), "r"(b1))

__device__ __forceinline__ uint32_t smem_to_u32(const void* p) {
    uint32_t a;
    asm("{ .reg .u64 t; cvta.to.shared.u64 t, %1; cvt.u32.u64 %0, t; }" : "=r"(a) : "l"(p));
    return a;
}

// ===========================================================================
// Kernel 0a: pack + split weights into g_bh/g_bl  [192][1024] K-major
// ===========================================================================
__global__ __launch_bounds__(256) void pack_w_kernel(
    const float* __restrict__ wq, const float* __restrict__ wk, const float* __restrict__ wv)
{
    int idx = blockIdx.x * 256 + threadIdx.x;   // 0 .. 192*1024-1
    int n = idx >> 10;
    int k = idx & 1023;
    const float* w = (n < 64) ? wq : (n < 128) ? wk : wv;
    float v  = w[k * Hdim + (n & 63)];
    __nv_bfloat16 hi = __float2bfloat16(v);
    __nv_bfloat16 lo = __float2bfloat16(v - __bfloat162float(hi));
    g_bh[idx] = hi;
    g_bl[idx] = lo;
}

// ===========================================================================
// Kernel 0b: split x into bf16 hi/lo
// ===========================================================================
__global__ __launch_bounds__(256) void xsplit_kernel(const float* __restrict__ x)
{
    int idx4 = blockIdx.x * 256 + threadIdx.x;      // one float4 per thread
    size_t base = (size_t)idx4 * 4;
    float4 v = *(const float4*)&x[base];
    union { __nv_bfloat16 b[4]; uint2 u; } uh, ul;
    float vv[4] = {v.x, v.y, v.z, v.w};
    #pragma unroll
    for (int i = 0; i < 4; i++) {
        __nv_bfloat16 hi = __float2bfloat16(vv[i]);
        uh.b[i] = hi;
        ul.b[i] = __float2bfloat16(vv[i] - __bfloat162float(hi));
    }
    *(uint2*)&g_xh[base] = uh.u;
    *(uint2*)&g_xl[base] = ul.u;
}

// ===========================================================================
// Kernel 1: projection GEMM via mma.sync bf16 (3-way split = near-fp32).
// D[16384 x 192] = X[16384 x 1024] @ B^T.  CTA tile 128m x 192n, BK=64,
// cp.async double-buffered.  8 warps as 2m x 4n -> warp tile 64 x 48.
// ===========================================================================
#define PROJ_PAD   72                       // bf16 elems per smem row (144 B)
#define A_SPLIT_B  (128 * PROJ_PAD * 2)     // 18432 B per A split tile
#define B_SPLIT_B  (192 * PROJ_PAD * 2)     // 27648 B per B split tile
#define STAGE_B    (2 * A_SPLIT_B + 2 * B_SPLIT_B)  // 92160
#define PROJ_SMEM  (2 * STAGE_B)            // 184320
#define NCHUNK     (Cdim / 64)              // 16

__global__ __launch_bounds__(256, 1) void proj_mma_kernel()
{
    extern __shared__ char smem[];
    const uint32_t sbase = smem_to_u32(smem);
    const int tid  = threadIdx.x;
    const int wid  = tid >> 5;
    const int lane = tid & 31;
    const int row0 = blockIdx.x * 128;

    const int wm = wid >> 2;        // 0..1 -> m offset wm*64
    const int wn = wid & 3;         // 0..3 -> n offset wn*48

    float acc[4][6][4];
    #pragma unroll
    for (int i = 0; i < 4; i++)
        #pragma unroll
        for (int j = 0; j < 6; j++)
            #pragma unroll
            for (int r = 0; r < 4; r++) acc[i][j][r] = 0.f;

    // ---- async-load one BK=64 chunk into stage (c & 1) ----
    auto issue_chunk = [&](int c) {
        const uint32_t sb = sbase + (uint32_t)(c & 1) * STAGE_B;
        const int k0 = c * 64;
        // A hi/lo: 128 rows x 128 B, 1024 segs each
        #pragma unroll
        for (int t = 0; t < 4; t++) {
            int seg = tid + t * 256;
            int r = seg >> 3, o8 = seg & 7;
            size_t ge = (size_t)(row0 + r) * Cdim + k0 + o8 * 8;
            CP_ASYNC16(sb + r * 144 + o8 * 16,              &g_xh[ge]);
            CP_ASYNC16(sb + A_SPLIT_B + r * 144 + o8 * 16,  &g_xl[ge]);
        }
        // B hi/lo: 192 rows x 128 B, 1536 segs each
        #pragma unroll
        for (int t = 0; t < 6; t++) {
            int seg = tid + t * 256;
            int r = seg >> 3, o8 = seg & 7;
            size_t ge = (size_t)r * Cdim + k0 + o8 * 8;
            CP_ASYNC16(sb + 2 * A_SPLIT_B + r * 144 + o8 * 16,              &g_bh[ge]);
            CP_ASYNC16(sb + 2 * A_SPLIT_B + B_SPLIT_B + r * 144 + o8 * 16,  &g_bl[ge]);
        }
        CP_COMMIT();
    };

    issue_chunk(0);

    const int rsel = lane & 15;                 // row within 16-block
    const int ksel = (lane < 16) ? 0 : 8;       // k sub-offset

    for (int c = 0; c < NCHUNK; c++) {
        if (c + 1 < NCHUNK) { issue_chunk(c + 1); CP_WAIT(1); }
        else                { CP_WAIT(0); }
        __syncthreads();

        const uint32_t sb = sbase + (uint32_t)(c & 1) * STAGE_B;
        const uint32_t Ah = sb;
        const uint32_t Al = sb + A_SPLIT_B;
        const uint32_t Bh = sb + 2 * A_SPLIT_B;
        const uint32_t Bl = sb + 2 * A_SPLIT_B + B_SPLIT_B;

        #pragma unroll
        for (int kk = 0; kk < 4; kk++) {        // 4 k16 steps in BK=64
            const uint32_t kb = (kk * 16 + ksel) * 2;
            uint32_t ah[4][4], al[4][4];
            #pragma unroll
            for (int i = 0; i < 4; i++) {
                uint32_t ro = (uint32_t)(wm * 64 + i * 16 + rsel) * 144 + kb;
                LDMATRIX_X4(ah[i][0], ah[i][1], ah[i][2], ah[i][3], Ah + ro);
                LDMATRIX_X4(al[i][0], al[i][1], al[i][2], al[i][3], Al + ro);
            }
            uint32_t bh[3][4], bl[3][4];
            #pragma unroll
            for (int p = 0; p < 3; p++) {
                uint32_t ro = (uint32_t)(wn * 48 + p * 16 + rsel) * 144 + kb;
                LDMATRIX_X4(bh[p][0], bh[p][1], bh[p][2], bh[p][3], Bh + ro);
                LDMATRIX_X4(bl[p][0], bl[p][1], bl[p][2], bl[p][3], Bl + ro);
            }
            #pragma unroll
            for (int i = 0; i < 4; i++)
                #pragma unroll
                for (int p = 0; p < 3; p++)
                    #pragma unroll
                    for (int h = 0; h < 2; h++) {
                        const int j = p * 2 + h;
                        MMA_BF16(acc[i][j], ah[i], bh[p][h], bh[p][h + 2]);  // hi*hi
                        MMA_BF16(acc[i][j], ah[i], bl[p][h], bl[p][h + 2]);  // hi*lo
                        MMA_BF16(acc[i][j], al[i], bh[p][h], bh[p][h + 2]);  // lo*hi
                    }
        }
        __syncthreads();
    }

    // Epilogue: scatter D to g_q / g_k / g_v
    #pragma unroll
    for (int i = 0; i < 4; i++) {
        const int rA = row0 + wm * 64 + i * 16 + (lane >> 2);
        #pragma unroll
        for (int j = 0; j < 6; j++) {
            const int col = wn * 48 + j * 8 + (lane & 3) * 2;
            float* dst = (col < 64) ? g_q : (col < 128) ? g_k : g_v;
            const int h = col & 63;
            *(float2*)&dst[(size_t)rA * Hdim + h]       = make_float2(acc[i][j][0], acc[i][j][1]);
            *(float2*)&dst[(size_t)(rA + 8) * Hdim + h] = make_float2(acc[i][j][2], acc[i][j][3]);
        }
    }
}

// ===========================================================================
// Kernel 2: flash attention (causal, online softmax) — SIMT, heavy-first.
// ===========================================================================
#define PADW 68
#define ATTN_SMEM (4 * 64 * PADW * (int)sizeof(float))   // 69632 bytes

__global__ __launch_bounds__(256) void attn_kernel(float* __restrict__ out)
{
    extern __shared__ float sm[];
    float (*qsT)[PADW] = (float(*)[PADW])(sm);
    float (*ksT)[PADW] = (float(*)[PADW])(sm + 64 * PADW);
    float (*vs )[PADW] = (float(*)[PADW])(sm + 2 * 64 * PADW);
    float (*ps )[PADW] = (float(*)[PADW])(sm + 3 * 64 * PADW);

    const int tid   = threadIdx.x;
    const int tx    = tid & 15;
    const int ty    = tid >> 4;
    const int qtile = (Tseq / 64 - 1) - blockIdx.x;   // heavy tiles first
    const int q0    = qtile * 64;
    const int b     = blockIdx.y;

    const float* qg = g_q + (size_t)b * Tseq * Hdim;
    const float* kg = g_k + (size_t)b * Tseq * Hdim;
    const float* vg = g_v + (size_t)b * Tseq * Hdim;

    #pragma unroll
    for (int t = 0; t < 4; t++) {
        int idx = tid + t * 256;
        int r   = idx >> 4;
        int h4  = idx & 15;
        float4 v = *(const float4*)&qg[(size_t)(q0 + r) * Hdim + h4 * 4];
        qsT[h4 * 4 + 0][r] = v.x * SCALE;
        qsT[h4 * 4 + 1][r] = v.y * SCALE;
        qsT[h4 * 4 + 2][r] = v.z * SCALE;
        qsT[h4 * 4 + 3][r] = v.w * SCALE;
    }

    float m[4], l[4], O[4][4];
    #pragma unroll
    for (int i = 0; i < 4; i++) {
        m[i] = -1e30f; l[i] = 0.f;
        #pragma unroll
        for (int j = 0; j < 4; j++) O[i][j] = 0.f;
    }

    const int ntiles = qtile + 1;
    for (int kt = 0; kt < ntiles; kt++) {
        const int k0 = kt * 64;
        __syncthreads();

        #pragma unroll
        for (int t = 0; t < 4; t++) {
            int idx = tid + t * 256;
            int r   = idx >> 4;
            int h4  = idx & 15;
            float4 kv = *(const float4*)&kg[(size_t)(k0 + r) * Hdim + h4 * 4];
            ksT[h4 * 4 + 0][r] = kv.x;
            ksT[h4 * 4 + 1][r] = kv.y;
            ksT[h4 * 4 + 2][r] = kv.z;
            ksT[h4 * 4 + 3][r] = kv.w;
            *(float4*)&vs[r][h4 * 4] = *(const float4*)&vg[(size_t)(k0 + r) * Hdim + h4 * 4];
        }
        __syncthreads();

        float S[4][4] = {};
        #pragma unroll
        for (int d = 0; d < 64; d++) {
            float4 qa = *(const float4*)&qsT[d][ty * 4];
            float4 kb = *(const float4*)&ksT[d][tx * 4];
            float qv[4] = {qa.x, qa.y, qa.z, qa.w};
            float kv[4] = {kb.x, kb.y, kb.z, kb.w};
            #pragma unroll
            for (int i = 0; i < 4; i++)
                #pragma unroll
                for (int j = 0; j < 4; j++)
                    S[i][j] += qv[i] * kv[j];
        }

        if (k0 == q0) {
            #pragma unroll
            for (int i = 0; i < 4; i++)
                #pragma unroll
                for (int j = 0; j < 4; j++)
                    if (k0 + tx * 4 + j > q0 + ty * 4 + i) S[i][j] = -1e30f;
        }

        #pragma unroll
        for (int i = 0; i < 4; i++) {
            float mloc = fmaxf(fmaxf(S[i][0], S[i][1]), fmaxf(S[i][2], S[i][3]));
            #pragma unroll
            for (int off = 8; off >= 1; off >>= 1)
                mloc = fmaxf(mloc, __shfl_xor_sync(0xffffffffu, mloc, off, 16));
            float mnew  = fmaxf(m[i], mloc);
            float alpha = __expf(m[i] - mnew);
            float lloc = 0.f;
            #pragma unroll
            for (int j = 0; j < 4; j++) {
                S[i][j] = __expf(S[i][j] - mnew);
                lloc += S[i][j];
            }
            #pragma unroll
            for (int off = 8; off >= 1; off >>= 1)
                lloc += __shfl_xor_sync(0xffffffffu, lloc, off, 16);
            l[i] = l[i] * alpha + lloc;
            m[i] = mnew;
            #pragma unroll
            for (int j = 0; j < 4; j++) O[i][j] *= alpha;
        }

        #pragma unroll
        for (int i = 0; i < 4; i++)
            *(float4*)&ps[ty * 4 + i][tx * 4] = make_float4(S[i][0], S[i][1], S[i][2], S[i][3]);
        __syncthreads();

        #pragma unroll
        for (int c = 0; c < 64; c++) {
            float pa[4];
            #pragma unroll
            for (int i = 0; i < 4; i++) pa[i] = ps[ty * 4 + i][c];
            float4 vb = *(const float4*)&vs[c][tx * 4];
            float vv[4] = {vb.x, vb.y, vb.z, vb.w};
            #pragma unroll
            for (int i = 0; i < 4; i++)
                #pragma unroll
                for (int j = 0; j < 4; j++)
                    O[i][j] += pa[i] * vv[j];
        }
    }

    #pragma unroll
    for (int i = 0; i < 4; i++) {
        float inv = 1.0f / l[i];
        size_t o = ((size_t)b * Tseq + q0 + ty * 4 + i) * Hdim + tx * 4;
        *(float4*)&out[o] = make_float4(O[i][0] * inv, O[i][1] * inv,
                                        O[i][2] * inv, O[i][3] * inv);
    }
}

// ===========================================================================
extern "C" void kernel_launch(void* const* d_in, const int* in_sizes, int n_in,
                              void* d_out, int out_size)
{
    const float* x  = (const float*)d_in[0];
    const float* wq = (const float*)d_in[1];
    const float* wk = (const float*)d_in[2];
    const float* wv = (const float*)d_in[3];
    float* out = (float*)d_out;

    cudaFuncSetAttribute(proj_mma_kernel, cudaFuncAttributeMaxDynamicSharedMemorySize,
                         PROJ_SMEM);
    cudaFuncSetAttribute(attn_kernel, cudaFuncAttributeMaxDynamicSharedMemorySize,
                         ATTN_SMEM);

    pack_w_kernel<<<(192 * Cdim) / 256, 256>>>(wq, wk, wv);
    xsplit_kernel<<<(BT * Cdim) / (256 * 4), 256>>>(x);
    proj_mma_kernel<<<BT / 128, 256, PROJ_SMEM>>>();
    attn_kernel<<<dim3(Tseq / 64, Bb), 256, ATTN_SMEM>>>(out);
}

// round 4
// speedup vs baseline: 2.6203x; 2.1714x over previous
#include <cuda_runtime.h>
#include <cuda_bf16.h>
#include <cstdint>

// Problem constants
#define Bb    8
#define Tseq  2048
#define Cdim  1024
#define Hdim  64
#define BT    (Bb * Tseq)
#define SCALE 0.125f
#define QT_N  32      // number of 64-row q tiles per batch
#define MAXCH 8       // max kv chunks (of 256) per q tile

// Scratch (device globals — no allocation allowed)
__device__ __align__(128) float g_v[BT * Hdim];
__device__ __align__(128) __nv_bfloat16 g_qh[BT * Hdim], g_ql[BT * Hdim];
__device__ __align__(128) __nv_bfloat16 g_kh[BT * Hdim], g_kl[BT * Hdim];
__device__ __align__(128) __nv_bfloat16 g_vTh[Bb * Hdim * Tseq], g_vTl[Bb * Hdim * Tseq];
__device__ __align__(128) __nv_bfloat16 g_xh[BT * Cdim], g_xl[BT * Cdim];
__device__ __align__(128) __nv_bfloat16 g_bh[192 * Cdim], g_bl[192 * Cdim];
// attention partials
__device__ float g_pO[(size_t)Bb * QT_N * MAXCH * 64 * 64];   // 33.5 MB
__device__ float g_pm[Bb * QT_N * MAXCH * 64];
__device__ float g_pl[Bb * QT_N * MAXCH * 64];

// ===========================================================================
// Generic-PTX tensor helpers (sm_80+ ISA)
// ===========================================================================
#define CP_ASYNC16(smem_u32, gptr) \
    asm volatile("cp.async.cg.shared.global [%0], [%1], 16;" \
                 :: "r"(smem_u32), "l"(gptr) : "memory")
#define CP_COMMIT() asm volatile("cp.async.commit_group;" ::: "memory")
#define CP_WAIT(N)  asm volatile("cp.async.wait_group %0;" :: "n"(N) : "memory")

#define LDMATRIX_X4(r0, r1, r2, r3, addr) \
    asm volatile("ldmatrix.sync.aligned.m8n8.x4.shared.b16 {%0,%1,%2,%3}, [%4];" \
                 : "=r"(r0), "=r"(r1), "=r"(r2), "=r"(r3) : "r"(addr))

#define MMA_BF16(d, a, b0, b1) \
    asm volatile("mma.sync.aligned.m16n8k16.row.col.f32.bf16.bf16.f32 " \
                 "{%0,%1,%2,%3}, {%4,%5,%6,%7}, {%8,%9}, {%0,%1,%2,%3};" \
                 : "+f"((d)[0]), "+f"((d)[1]), "+f"((d)[2]), "+f"((d)[3]) \
                 : "r"((a)[0]), "r"((a)[1]), "r"((a)[2]), "r"((a)[3]), \
                   "r"(b0), "r"(b1))

__device__ __forceinline__ uint32_t smem_to_u32(const void* p) {
    uint32_t a;
    asm("{ .reg .u64 t; cvta.to.shared.u64 t, %1; cvt.u32.u64 %0, t; }" : "=r"(a) : "l"(p));
    return a;
}

// split two floats into packed bf16 hi + bf16 lo residual (x -> low half)
__device__ __forceinline__ void split2(float x, float y, uint32_t& hi, uint32_t& lo) {
    __nv_bfloat16 hx = __float2bfloat16(x), hy = __float2bfloat16(y);
    __nv_bfloat162 h2 = __halves2bfloat162(hx, hy);
    hi = *(uint32_t*)&h2;
    __nv_bfloat162 l2 = __halves2bfloat162(
        __float2bfloat16(x - __bfloat162float(hx)),
        __float2bfloat16(y - __bfloat162float(hy)));
    lo = *(uint32_t*)&l2;
}

// ===========================================================================
// Kernel 0a: pack + split weights into g_bh/g_bl  [192][1024] K-major
// ===========================================================================
__global__ __launch_bounds__(256) void pack_w_kernel(
    const float* __restrict__ wq, const float* __restrict__ wk, const float* __restrict__ wv)
{
    int idx = blockIdx.x * 256 + threadIdx.x;
    int n = idx >> 10;
    int k = idx & 1023;
    const float* w = (n < 64) ? wq : (n < 128) ? wk : wv;
    float v  = w[k * Hdim + (n & 63)];
    __nv_bfloat16 hi = __float2bfloat16(v);
    g_bh[idx] = hi;
    g_bl[idx] = __float2bfloat16(v - __bfloat162float(hi));
}

// ===========================================================================
// Kernel 0b: split x into bf16 hi/lo
// ===========================================================================
__global__ __launch_bounds__(256) void xsplit_kernel(const float* __restrict__ x)
{
    int idx4 = blockIdx.x * 256 + threadIdx.x;
    size_t base = (size_t)idx4 * 4;
    float4 v = *(const float4*)&x[base];
    union { __nv_bfloat16 b[4]; uint2 u; } uh, ul;
    float vv[4] = {v.x, v.y, v.z, v.w};
    #pragma unroll
    for (int i = 0; i < 4; i++) {
        __nv_bfloat16 hi = __float2bfloat16(vv[i]);
        uh.b[i] = hi;
        ul.b[i] = __float2bfloat16(vv[i] - __bfloat162float(hi));
    }
    *(uint2*)&g_xh[base] = uh.u;
    *(uint2*)&g_xl[base] = ul.u;
}

// ===========================================================================
// Kernel 1: projection GEMM via mma.sync bf16 (3-way split).
// Epilogue emits q (pre-scaled) and k as bf16 hi/lo, v as fp32.
// ===========================================================================
#define PROJ_PAD   72
#define A_SPLIT_B  (128 * PROJ_PAD * 2)
#define B_SPLIT_B  (192 * PROJ_PAD * 2)
#define STAGE_B    (2 * A_SPLIT_B + 2 * B_SPLIT_B)
#define PROJ_SMEM  (2 * STAGE_B)
#define NCHUNK     (Cdim / 64)

__global__ __launch_bounds__(256, 1) void proj_mma_kernel()
{
    extern __shared__ char smem[];
    const uint32_t sbase = smem_to_u32(smem);
    const int tid  = threadIdx.x;
    const int wid  = tid >> 5;
    const int lane = tid & 31;
    const int row0 = blockIdx.x * 128;

    const int wm = wid >> 2;
    const int wn = wid & 3;

    float acc[4][6][4];
    #pragma unroll
    for (int i = 0; i < 4; i++)
        #pragma unroll
        for (int j = 0; j < 6; j++)
            #pragma unroll
            for (int r = 0; r < 4; r++) acc[i][j][r] = 0.f;

    auto issue_chunk = [&](int c) {
        const uint32_t sb = sbase + (uint32_t)(c & 1) * STAGE_B;
        const int k0 = c * 64;
        #pragma unroll
        for (int t = 0; t < 4; t++) {
            int seg = tid + t * 256;
            int r = seg >> 3, o8 = seg & 7;
            size_t ge = (size_t)(row0 + r) * Cdim + k0 + o8 * 8;
            CP_ASYNC16(sb + r * 144 + o8 * 16,              &g_xh[ge]);
            CP_ASYNC16(sb + A_SPLIT_B + r * 144 + o8 * 16,  &g_xl[ge]);
        }
        #pragma unroll
        for (int t = 0; t < 6; t++) {
            int seg = tid + t * 256;
            int r = seg >> 3, o8 = seg & 7;
            size_t ge = (size_t)r * Cdim + k0 + o8 * 8;
            CP_ASYNC16(sb + 2 * A_SPLIT_B + r * 144 + o8 * 16,              &g_bh[ge]);
            CP_ASYNC16(sb + 2 * A_SPLIT_B + B_SPLIT_B + r * 144 + o8 * 16,  &g_bl[ge]);
        }
        CP_COMMIT();
    };

    issue_chunk(0);

    const int rsel = lane & 15;
    const int ksel = (lane < 16) ? 0 : 8;

    for (int c = 0; c < NCHUNK; c++) {
        if (c + 1 < NCHUNK) { issue_chunk(c + 1); CP_WAIT(1); }
        else                { CP_WAIT(0); }
        __syncthreads();

        const uint32_t sb = sbase + (uint32_t)(c & 1) * STAGE_B;
        const uint32_t Ah = sb;
        const uint32_t Al = sb + A_SPLIT_B;
        const uint32_t Bh = sb + 2 * A_SPLIT_B;
        const uint32_t Bl = sb + 2 * A_SPLIT_B + B_SPLIT_B;

        #pragma unroll
        for (int kk = 0; kk < 4; kk++) {
            const uint32_t kb = (kk * 16 + ksel) * 2;
            uint32_t ah[4][4], al[4][4];
            #pragma unroll
            for (int i = 0; i < 4; i++) {
                uint32_t ro = (uint32_t)(wm * 64 + i * 16 + rsel) * 144 + kb;
                LDMATRIX_X4(ah[i][0], ah[i][1], ah[i][2], ah[i][3], Ah + ro);
                LDMATRIX_X4(al[i][0], al[i][1], al[i][2], al[i][3], Al + ro);
            }
            uint32_t bh[3][4], bl[3][4];
            #pragma unroll
            for (int p = 0; p < 3; p++) {
                uint32_t ro = (uint32_t)(wn * 48 + p * 16 + rsel) * 144 + kb;
                LDMATRIX_X4(bh[p][0], bh[p][1], bh[p][2], bh[p][3], Bh + ro);
                LDMATRIX_X4(bl[p][0], bl[p][1], bl[p][2], bl[p][3], Bl + ro);
            }
            #pragma unroll
            for (int i = 0; i < 4; i++)
                #pragma unroll
                for (int p = 0; p < 3; p++)
                    #pragma unroll
                    for (int h = 0; h < 2; h++) {
                        const int j = p * 2 + h;
                        MMA_BF16(acc[i][j], ah[i], bh[p][h], bh[p][h + 2]);
                        MMA_BF16(acc[i][j], ah[i], bl[p][h], bl[p][h + 2]);
                        MMA_BF16(acc[i][j], al[i], bh[p][h], bh[p][h + 2]);
                    }
        }
        __syncthreads();
    }

    // Epilogue: q -> scaled bf16 hi/lo, k -> bf16 hi/lo, v -> fp32
    #pragma unroll
    for (int i = 0; i < 4; i++) {
        const int rA = row0 + wm * 64 + i * 16 + (lane >> 2);
        #pragma unroll
        for (int j = 0; j < 6; j++) {
            const int col = wn * 48 + j * 8 + (lane & 3) * 2;
            float v00 = acc[i][j][0], v01 = acc[i][j][1];
            float v10 = acc[i][j][2], v11 = acc[i][j][3];
            if (col < 64) {
                uint32_t hi, lo;
                size_t o0 = (size_t)rA * Hdim + col;
                size_t o1 = (size_t)(rA + 8) * Hdim + col;
                split2(v00 * SCALE, v01 * SCALE, hi, lo);
                *(uint32_t*)&g_qh[o0] = hi; *(uint32_t*)&g_ql[o0] = lo;
                split2(v10 * SCALE, v11 * SCALE, hi, lo);
                *(uint32_t*)&g_qh[o1] = hi; *(uint32_t*)&g_ql[o1] = lo;
            } else if (col < 128) {
                uint32_t hi, lo;
                const int h = col - 64;
                size_t o0 = (size_t)rA * Hdim + h;
                size_t o1 = (size_t)(rA + 8) * Hdim + h;
                split2(v00, v01, hi, lo);
                *(uint32_t*)&g_kh[o0] = hi; *(uint32_t*)&g_kl[o0] = lo;
                split2(v10, v11, hi, lo);
                *(uint32_t*)&g_kh[o1] = hi; *(uint32_t*)&g_kl[o1] = lo;
            } else {
                const int h = col - 128;
                *(float2*)&g_v[(size_t)rA * Hdim + h]       = make_float2(v00, v01);
                *(float2*)&g_v[(size_t)(rA + 8) * Hdim + h] = make_float2(v10, v11);
            }
        }
    }
}

// ===========================================================================
// Kernel 1b: split + transpose V -> g_vT{h,l}[b][h][t]
// ===========================================================================
__global__ __launch_bounds__(256) void vsplitT_kernel()
{
    int idx = blockIdx.x * 256 + threadIdx.x;    // = b<<17 | h<<11 | t
    int t = idx & (Tseq - 1);
    int h = (idx >> 11) & 63;
    int b = idx >> 17;
    float v = g_v[((size_t)(b * Tseq + t)) * Hdim + h];
    __nv_bfloat16 hi = __float2bfloat16(v);
    g_vTh[idx] = hi;
    g_vTl[idx] = __float2bfloat16(v - __bfloat162float(hi));
}

// ===========================================================================
// Kernel 2: flash-attention work units on mma.sync bf16.
// Unit = (batch, qtile of 64 rows, kv-chunk of up to 4x64). 4 warps, each
// owns 16 q rows. Writes partial (unnormalized O, m, l) to scratch.
// ===========================================================================
#define ROWB   144                          // smem row stride bytes (72 bf16)
#define QH_OFF 0
#define QL_OFF 9216
#define STG_OFF 18432
#define STG_SZ  36864                       // Kh | Kl | VTh | VTl (9216 each)
#define ATTN_SMEM (STG_OFF + 2 * STG_SZ)    // 92160

__global__ __launch_bounds__(128) void attn_mma_kernel()
{
    extern __shared__ char smem[];
    const uint32_t sb = smem_to_u32(smem);
    const int tid  = threadIdx.x;
    const int w    = tid >> 5;
    const int lane = tid & 31;
    const int b    = blockIdx.y;

    // map blockIdx.x -> (qt, chunk), heavy qtiles first
    int u = blockIdx.x, qt = QT_N - 1, chunk = 0;
    for (;;) {
        int nc = (qt + 4) >> 2;
        if (u < nc) { chunk = u; break; }
        u -= nc; qt--;
    }
    const int nsub = min(4, (qt + 1) - chunk * 4);
    const int sub0 = chunk * 4;              // first kv subtile index
    const int q0   = qt * 64;

    // ---- stage Q (hi+lo) ----
    {
        const __nv_bfloat16* qhp = g_qh + ((size_t)(b * Tseq + q0)) * Hdim;
        const __nv_bfloat16* qlp = g_ql + ((size_t)(b * Tseq + q0)) * Hdim;
        #pragma unroll
        for (int t = 0; t < 4; t++) {
            int seg = tid + t * 128;         // 0..511
            int r = seg >> 3, o = seg & 7;
            CP_ASYNC16(sb + QH_OFF + r * ROWB + o * 16, qhp + r * 64 + o * 8);
            CP_ASYNC16(sb + QL_OFF + r * ROWB + o * 16, qlp + r * 64 + o * 8);
        }
        CP_COMMIT();
    }

    auto stage = [&](int s, int buf) {       // s = global kv subtile index
        const uint32_t o = sb + STG_OFF + (uint32_t)buf * STG_SZ;
        const __nv_bfloat16* kh = g_kh + ((size_t)(b * Tseq + s * 64)) * Hdim;
        const __nv_bfloat16* kl = g_kl + ((size_t)(b * Tseq + s * 64)) * Hdim;
        #pragma unroll
        for (int t = 0; t < 4; t++) {
            int seg = tid + t * 128;
            int r = seg >> 3, c = seg & 7;
            CP_ASYNC16(o + r * ROWB + c * 16,        kh + r * 64 + c * 8);
            CP_ASYNC16(o + 9216 + r * ROWB + c * 16, kl + r * 64 + c * 8);
        }
        const __nv_bfloat16* vth = g_vTh + (size_t)b * Hdim * Tseq + s * 64;
        const __nv_bfloat16* vtl = g_vTl + (size_t)b * Hdim * Tseq + s * 64;
        #pragma unroll
        for (int t = 0; t < 4; t++) {
            int seg = tid + t * 128;
            int r = seg >> 3, c = seg & 7;   // r = h row
            CP_ASYNC16(o + 18432 + r * ROWB + c * 16, vth + (size_t)r * Tseq + c * 8);
            CP_ASYNC16(o + 27648 + r * ROWB + c * 16, vtl + (size_t)r * Tseq + c * 8);
        }
        CP_COMMIT();
    };

    stage(sub0, 0);
    if (nsub > 1) stage(sub0 + 1, 1);

    const int rsel  = lane & 15;
    const int ksel2 = (lane < 16) ? 0 : 16;  // byte offset of k-half

    // wait Q + stage0 (leave at most stage1 pending), load Q frags
    if (nsub > 1) { CP_WAIT(1); } else { CP_WAIT(0); }
    __syncthreads();

    uint32_t qfh[4][4], qfl[4][4];
    #pragma unroll
    for (int ks = 0; ks < 4; ks++) {
        uint32_t ro = sb + (uint32_t)(w * 16 + rsel) * ROWB + ks * 32 + ksel2;
        LDMATRIX_X4(qfh[ks][0], qfh[ks][1], qfh[ks][2], qfh[ks][3], ro + QH_OFF);
        LDMATRIX_X4(qfl[ks][0], qfl[ks][1], qfl[ks][2], qfl[ks][3], ro + QL_OFF);
    }

    float m0 = -1e30f, m1 = -1e30f, l0 = 0.f, l1 = 0.f;
    float O[8][4];
    #pragma unroll
    for (int f = 0; f < 8; f++)
        #pragma unroll
        for (int r = 0; r < 4; r++) O[f][r] = 0.f;

    const int gr  = lane >> 2;       // row-in-16 (and +8)
    const int gc2 = (lane & 3) * 2;  // col pair base

    for (int i = 0; i < nsub; i++) {
        if (i > 0) {                 // buf i staged in previous iteration
            if (i + 1 < nsub) CP_WAIT(1); else CP_WAIT(0);
            __syncthreads();
        }
        const uint32_t kb = sb + STG_OFF + (uint32_t)(i & 1) * STG_SZ;
        const int sglob = sub0 + i;

        // ---- S = Q K^T (3-way split) ----
        float S[8][4];
        #pragma unroll
        for (int f = 0; f < 8; f++)
            #pragma unroll
            for (int r = 0; r < 4; r++) S[f][r] = 0.f;

        #pragma unroll
        for (int ks = 0; ks < 4; ks++) {
            #pragma unroll
            for (int nt = 0; nt < 4; nt++) {
                uint32_t ro = kb + (uint32_t)(nt * 16 + rsel) * ROWB + ks * 32 + ksel2;
                uint32_t bh[4], bl[4];
                LDMATRIX_X4(bh[0], bh[1], bh[2], bh[3], ro);
                LDMATRIX_X4(bl[0], bl[1], bl[2], bl[3], ro + 9216);
                #pragma unroll
                for (int h = 0; h < 2; h++) {
                    MMA_BF16(S[nt * 2 + h], qfh[ks], bh[h], bh[h + 2]);
                    MMA_BF16(S[nt * 2 + h], qfh[ks], bl[h], bl[h + 2]);
                    MMA_BF16(S[nt * 2 + h], qfl[ks], bh[h], bh[h + 2]);
                }
            }
        }

        // ---- causal mask (diagonal subtile only) ----
        if (sglob == qt) {
            const int r0 = q0 + w * 16 + gr;
            #pragma unroll
            for (int f = 0; f < 8; f++) {
                const int c = q0 + f * 8 + gc2;
                if (c     > r0)     S[f][0] = -1e30f;
                if (c + 1 > r0)     S[f][1] = -1e30f;
                if (c     > r0 + 8) S[f][2] = -1e30f;
                if (c + 1 > r0 + 8) S[f][3] = -1e30f;
            }
        }

        // ---- online softmax ----
        float mx0 = -1e30f, mx1 = -1e30f;
        #pragma unroll
        for (int f = 0; f < 8; f++) {
            mx0 = fmaxf(mx0, fmaxf(S[f][0], S[f][1]));
            mx1 = fmaxf(mx1, fmaxf(S[f][2], S[f][3]));
        }
        mx0 = fmaxf(mx0, __shfl_xor_sync(0xffffffffu, mx0, 1));
        mx0 = fmaxf(mx0, __shfl_xor_sync(0xffffffffu, mx0, 2));
        mx1 = fmaxf(mx1, __shfl_xor_sync(0xffffffffu, mx1, 1));
        mx1 = fmaxf(mx1, __shfl_xor_sync(0xffffffffu, mx1, 2));
        const float mn0 = fmaxf(m0, mx0), mn1 = fmaxf(m1, mx1);
        const float a0 = __expf(m0 - mn0), a1 = __expf(m1 - mn1);
        float s0 = 0.f, s1 = 0.f;
        #pragma unroll
        for (int f = 0; f < 8; f++) {
            S[f][0] = __expf(S[f][0] - mn0);
            S[f][1] = __expf(S[f][1] - mn0);
            S[f][2] = __expf(S[f][2] - mn1);
            S[f][3] = __expf(S[f][3] - mn1);
            s0 += S[f][0] + S[f][1];
            s1 += S[f][2] + S[f][3];
        }
        s0 += __shfl_xor_sync(0xffffffffu, s0, 1);
        s0 += __shfl_xor_sync(0xffffffffu, s0, 2);
        s1 += __shfl_xor_sync(0xffffffffu, s1, 1);
        s1 += __shfl_xor_sync(0xffffffffu, s1, 2);
        l0 = l0 * a0 + s0;
        l1 = l1 * a1 + s1;
        m0 = mn0; m1 = mn1;
        #pragma unroll
        for (int f = 0; f < 8; f++) {
            O[f][0] *= a0; O[f][1] *= a0;
            O[f][2] *= a1; O[f][3] *= a1;
        }

        // ---- O += P V (3-way split), A-frags built from S accumulators ----
        #pragma unroll
        for (int ks = 0; ks < 4; ks++) {
            uint32_t pha[4], pla[4];
            split2(S[2 * ks][0],     S[2 * ks][1],     pha[0], pla[0]);
            split2(S[2 * ks][2],     S[2 * ks][3],     pha[1], pla[1]);
            split2(S[2 * ks + 1][0], S[2 * ks + 1][1], pha[2], pla[2]);
            split2(S[2 * ks + 1][2], S[2 * ks + 1][3], pha[3], pla[3]);
            #pragma unroll
            for (int ht = 0; ht < 4; ht++) {
                uint32_t ro = kb + 18432u + (uint32_t)(ht * 16 + rsel) * ROWB + ks * 32 + ksel2;
                uint32_t vh[4], vl[4];
                LDMATRIX_X4(vh[0], vh[1], vh[2], vh[3], ro);
                LDMATRIX_X4(vl[0], vl[1], vl[2], vl[3], ro + 9216);
                #pragma unroll
                for (int h = 0; h < 2; h++) {
                    MMA_BF16(O[ht * 2 + h], pha, vh[h], vh[h + 2]);
                    MMA_BF16(O[ht * 2 + h], pha, vl[h], vl[h + 2]);
                    MMA_BF16(O[ht * 2 + h], pla, vh[h], vh[h + 2]);
                }
            }
        }

        __syncthreads();                      // all warps done with buf i
        if (i + 2 < nsub) stage(sub0 + i + 2, i & 1);
    }

    // ---- epilogue: write partials ----
    {
        const size_t base = ((size_t)((b * QT_N + qt) * MAXCH + chunk)) * 4096;
        const int r0 = w * 16 + gr;
        #pragma unroll
        for (int f = 0; f < 8; f++) {
            const int h = f * 8 + gc2;
            *(float2*)&g_pO[base + (size_t)r0 * 64 + h]       = make_float2(O[f][0], O[f][1]);
            *(float2*)&g_pO[base + (size_t)(r0 + 8) * 64 + h] = make_float2(O[f][2], O[f][3]);
        }
        if ((lane & 3) == 0) {
            const size_t sbs = (size_t)((b * QT_N + qt) * MAXCH + chunk) * 64;
            g_pm[sbs + r0]     = m0;  g_pm[sbs + r0 + 8] = m1;
            g_pl[sbs + r0]     = l0;  g_pl[sbs + r0 + 8] = l1;
        }
    }
}

// ===========================================================================
// Kernel 3: combine partials -> final output
// ===========================================================================
__global__ __launch_bounds__(256) void combine_kernel(float* __restrict__ out)
{
    int idx = blockIdx.x * 256 + threadIdx.x;   // (b, q, h4)
    int h4  = idx & 15;
    int q   = (idx >> 4) & (Tseq - 1);
    int b   = idx >> 15;
    int qt  = q >> 6;
    int row = q & 63;
    int nc  = (qt + 4) >> 2;

    const size_t sbs = (size_t)(b * QT_N + qt) * MAXCH * 64 + row;
    float M = -1e30f;
    for (int c = 0; c < nc; c++) M = fmaxf(M, g_pm[sbs + c * 64]);
    float L = 0.f;
    float wgt[MAXCH];
    for (int c = 0; c < nc; c++) {
        wgt[c] = __expf(g_pm[sbs + c * 64] - M);
        L += g_pl[sbs + c * 64] * wgt[c];
    }
    float ox = 0.f, oy = 0.f, oz = 0.f, ow = 0.f;
    const size_t ob = (size_t)(b * QT_N + qt) * MAXCH * 4096 + (size_t)row * 64 + h4 * 4;
    for (int c = 0; c < nc; c++) {
        float4 p = *(const float4*)&g_pO[ob + (size_t)c * 4096];
        ox += wgt[c] * p.x; oy += wgt[c] * p.y;
        oz += wgt[c] * p.z; ow += wgt[c] * p.w;
    }
    const float inv = 1.0f / L;
    *(float4*)&out[((size_t)(b * Tseq + q)) * Hdim + h4 * 4] =
        make_float4(ox * inv, oy * inv, oz * inv, ow * inv);
}

// ===========================================================================
extern "C" void kernel_launch(void* const* d_in, const int* in_sizes, int n_in,
                              void* d_out, int out_size)
{
    const float* x  = (const float*)d_in[0];
    const float* wq = (const float*)d_in[1];
    const float* wk = (const float*)d_in[2];
    const float* wv = (const float*)d_in[3];
    float* out = (float*)d_out;

    cudaFuncSetAttribute(proj_mma_kernel, cudaFuncAttributeMaxDynamicSharedMemorySize,
                         PROJ_SMEM);
    cudaFuncSetAttribute(attn_mma_kernel, cudaFuncAttributeMaxDynamicSharedMemorySize,
                         ATTN_SMEM);

    pack_w_kernel<<<(192 * Cdim) / 256, 256>>>(wq, wk, wv);
    xsplit_kernel<<<(BT * Cdim) / (256 * 4), 256>>>(x);
    proj_mma_kernel<<<BT / 128, 256, PROJ_SMEM>>>();
    vsplitT_kernel<<<(BT * Hdim) / 256, 256>>>();
    attn_mma_kernel<<<dim3(144, Bb), 128, ATTN_SMEM>>>();
    combine_kernel<<<(Bb * Tseq * 16) / 256, 256>>>(out);
}

// round 5
// speedup vs baseline: 3.0273x; 1.1553x over previous
#include <cuda_runtime.h>
#include <cuda_bf16.h>
#include <cstdint>

// Problem constants
#define Bb    8
#define Tseq  2048
#define Cdim  1024
#define Hdim  64
#define BT    (Bb * Tseq)
#define SCALE 0.125f
#define QT_N  32      // number of 64-row q tiles per batch
#define MAXCH 8       // max kv chunks (of 256) per q tile

// Scratch (device globals — no allocation allowed)
__device__ __align__(128) __nv_bfloat16 g_qh[BT * Hdim], g_ql[BT * Hdim];
__device__ __align__(128) __nv_bfloat16 g_kh[BT * Hdim], g_kl[BT * Hdim];
__device__ __align__(128) __nv_bfloat16 g_vh[BT * Hdim], g_vl[BT * Hdim];
__device__ __align__(128) __nv_bfloat16 g_bh[192 * Cdim], g_bl[192 * Cdim];
// attention partials
__device__ float g_pO[(size_t)Bb * QT_N * MAXCH * 64 * 64];
__device__ float g_pm[Bb * QT_N * MAXCH * 64];
__device__ float g_pl[Bb * QT_N * MAXCH * 64];

// ===========================================================================
// Generic-PTX tensor helpers (sm_80+ ISA)
// ===========================================================================
#define CP_ASYNC16(smem_u32, gptr) \
    asm volatile("cp.async.cg.shared.global [%0], [%1], 16;" \
                 :: "r"(smem_u32), "l"(gptr) : "memory")
#define CP_COMMIT() asm volatile("cp.async.commit_group;" ::: "memory")
#define CP_WAIT(N)  asm volatile("cp.async.wait_group %0;" :: "n"(N) : "memory")

#define LDMATRIX_X4(r0, r1, r2, r3, addr) \
    asm volatile("ldmatrix.sync.aligned.m8n8.x4.shared.b16 {%0,%1,%2,%3}, [%4];" \
                 : "=r"(r0), "=r"(r1), "=r"(r2), "=r"(r3) : "r"(addr))

#define LDMATRIX_X4_TRANS(r0, r1, r2, r3, addr) \
    asm volatile("ldmatrix.sync.aligned.m8n8.x4.trans.shared.b16 {%0,%1,%2,%3}, [%4];" \
                 : "=r"(r0), "=r"(r1), "=r"(r2), "=r"(r3) : "r"(addr))

#define MMA_BF16(d, a, b0, b1) \
    asm volatile("mma.sync.aligned.m16n8k16.row.col.f32.bf16.bf16.f32 " \
                 "{%0,%1,%2,%3}, {%4,%5,%6,%7}, {%8,%9}, {%0,%1,%2,%3};" \
                 : "+f"((d)[0]), "+f"((d)[1]), "+f"((d)[2]), "+f"((d)[3]) \
                 : "r"((a)[0]), "r"((a)[1]), "r"((a)[2]), "r"((a)[3]), \
                   "r"(b0), "r"(b1))

__device__ __forceinline__ uint32_t smem_to_u32(const void* p) {
    uint32_t a;
    asm("{ .reg .u64 t; cvta.to.shared.u64 t, %1; cvt.u32.u64 %0, t; }" : "=r"(a) : "l"(p));
    return a;
}

__device__ __forceinline__ void split2(float x, float y, uint32_t& hi, uint32_t& lo) {
    __nv_bfloat16 hx = __float2bfloat16(x), hy = __float2bfloat16(y);
    __nv_bfloat162 h2 = __halves2bfloat162(hx, hy);
    hi = *(uint32_t*)&h2;
    __nv_bfloat162 l2 = __halves2bfloat162(
        __float2bfloat16(x - __bfloat162float(hx)),
        __float2bfloat16(y - __bfloat162float(hy)));
    lo = *(uint32_t*)&l2;
}

// ===========================================================================
// Kernel 0: pack + split weights into g_bh/g_bl  [192][1024] K-major
// ===========================================================================
__global__ __launch_bounds__(256) void pack_w_kernel(
    const float* __restrict__ wq, const float* __restrict__ wk, const float* __restrict__ wv)
{
    int idx = blockIdx.x * 256 + threadIdx.x;
    int n = idx >> 10;
    int k = idx & 1023;
    const float* w = (n < 64) ? wq : (n < 128) ? wk : wv;
    float v  = w[k * Hdim + (n & 63)];
    __nv_bfloat16 hi = __float2bfloat16(v);
    g_bh[idx] = hi;
    g_bl[idx] = __float2bfloat16(v - __bfloat162float(hi));
}

// ===========================================================================
// Kernel 1: projection GEMM via mma.sync bf16 (3-way split), with fp32 x
// loaded raw and split to bf16 hi/lo in-kernel (no xsplit prepass).
// CTA tile 128m x 192n, BK=64, raw-x single buffered, split tiles + B tiles
// double buffered.  8 warps as 2m x 4n -> warp tile 64 x 48.
// ===========================================================================
#define ROWB144    144
#define AH_OFF     0                      // 2 x 18432
#define AL_OFF     36864                  // 2 x 18432
#define BH_OFF     73728                  // 2 x 27648
#define BL_OFF     129024                 // 2 x 27648
#define RAW_OFF    184320                 // 32768
#define PROJ_SMEM  217088
#define A_STG      18432
#define B_STG      27648
#define NCHUNK     (Cdim / 64)            // 16

__global__ __launch_bounds__(256, 1) void proj_mma_kernel(const float* __restrict__ x)
{
    extern __shared__ char smem[];
    const uint32_t sb = smem_to_u32(smem);
    const int tid  = threadIdx.x;
    const int wid  = tid >> 5;
    const int lane = tid & 31;
    const int row0 = blockIdx.x * 128;

    const int wm = wid >> 2;
    const int wn = wid & 3;

    float acc[4][6][4];
    #pragma unroll
    for (int i = 0; i < 4; i++)
        #pragma unroll
        for (int j = 0; j < 6; j++)
            #pragma unroll
            for (int r = 0; r < 4; r++) acc[i][j][r] = 0.f;

    // issue raw-x (fp32) + split B tiles for chunk c
    auto issue_chunk = [&](int c) {
        const int k0 = c * 64;
        const int s  = c & 1;
        // raw x: 128 rows x 256 B -> 2048 16B segs, 8/thread
        #pragma unroll
        for (int t = 0; t < 8; t++) {
            int seg = tid + t * 256;
            int r = seg >> 4, o = seg & 15;
            CP_ASYNC16(sb + RAW_OFF + r * 256 + o * 16,
                       &x[(size_t)(row0 + r) * Cdim + k0 + o * 4]);
        }
        // B hi/lo: 192 rows x 128 B each
        #pragma unroll
        for (int t = 0; t < 6; t++) {
            int seg = tid + t * 256;
            int r = seg >> 3, o8 = seg & 7;
            size_t ge = (size_t)r * Cdim + k0 + o8 * 8;
            CP_ASYNC16(sb + BH_OFF + s * B_STG + r * ROWB144 + o8 * 16, &g_bh[ge]);
            CP_ASYNC16(sb + BL_OFF + s * B_STG + r * ROWB144 + o8 * 16, &g_bl[ge]);
        }
        CP_COMMIT();
    };

    issue_chunk(0);

    const int rsel = lane & 15;
    const int ksel = (lane < 16) ? 0 : 8;

    for (int c = 0; c < NCHUNK; c++) {
        const int s = c & 1;
        CP_WAIT(0);
        __syncthreads();

        // convert raw fp32 -> Ah/Al stage s  (16 float2 per thread)
        #pragma unroll
        for (int t = 0; t < 16; t++) {
            int seg = tid + t * 256;          // 0..4095
            int r = seg >> 5, kp = seg & 31;
            float2 v = *(const float2*)(smem + RAW_OFF + r * 256 + kp * 8);
            uint32_t hi, lo;
            split2(v.x, v.y, hi, lo);
            *(uint32_t*)(smem + AH_OFF + s * A_STG + r * ROWB144 + kp * 4) = hi;
            *(uint32_t*)(smem + AL_OFF + s * A_STG + r * ROWB144 + kp * 4) = lo;
        }
        __syncthreads();                       // splits visible; raw buffer free

        if (c + 1 < NCHUNK) issue_chunk(c + 1);

        const uint32_t Ah = sb + AH_OFF + s * A_STG;
        const uint32_t Al = sb + AL_OFF + s * A_STG;
        const uint32_t Bh = sb + BH_OFF + s * B_STG;
        const uint32_t Bl = sb + BL_OFF + s * B_STG;

        #pragma unroll
        for (int kk = 0; kk < 4; kk++) {
            const uint32_t kb = (kk * 16 + ksel) * 2;
            uint32_t ah[4][4], al[4][4];
            #pragma unroll
            for (int i = 0; i < 4; i++) {
                uint32_t ro = (uint32_t)(wm * 64 + i * 16 + rsel) * ROWB144 + kb;
                LDMATRIX_X4(ah[i][0], ah[i][1], ah[i][2], ah[i][3], Ah + ro);
                LDMATRIX_X4(al[i][0], al[i][1], al[i][2], al[i][3], Al + ro);
            }
            uint32_t bh[3][4], bl[3][4];
            #pragma unroll
            for (int p = 0; p < 3; p++) {
                uint32_t ro = (uint32_t)(wn * 48 + p * 16 + rsel) * ROWB144 + kb;
                LDMATRIX_X4(bh[p][0], bh[p][1], bh[p][2], bh[p][3], Bh + ro);
                LDMATRIX_X4(bl[p][0], bl[p][1], bl[p][2], bl[p][3], Bl + ro);
            }
            #pragma unroll
            for (int i = 0; i < 4; i++)
                #pragma unroll
                for (int p = 0; p < 3; p++)
                    #pragma unroll
                    for (int h = 0; h < 2; h++) {
                        const int j = p * 2 + h;
                        MMA_BF16(acc[i][j], ah[i], bh[p][h], bh[p][h + 2]);
                        MMA_BF16(acc[i][j], ah[i], bl[p][h], bl[p][h + 2]);
                        MMA_BF16(acc[i][j], al[i], bh[p][h], bh[p][h + 2]);
                    }
        }
        __syncthreads();
    }

    // Epilogue: q -> scaled bf16 hi/lo; k, v -> bf16 hi/lo (natural [t][h])
    #pragma unroll
    for (int i = 0; i < 4; i++) {
        const int rA = row0 + wm * 64 + i * 16 + (lane >> 2);
        #pragma unroll
        for (int j = 0; j < 6; j++) {
            const int col = wn * 48 + j * 8 + (lane & 3) * 2;
            float v00 = acc[i][j][0], v01 = acc[i][j][1];
            float v10 = acc[i][j][2], v11 = acc[i][j][3];
            uint32_t hi, lo;
            const int h = col & 63;
            size_t o0 = (size_t)rA * Hdim + h;
            size_t o1 = (size_t)(rA + 8) * Hdim + h;
            if (col < 64) {
                split2(v00 * SCALE, v01 * SCALE, hi, lo);
                *(uint32_t*)&g_qh[o0] = hi; *(uint32_t*)&g_ql[o0] = lo;
                split2(v10 * SCALE, v11 * SCALE, hi, lo);
                *(uint32_t*)&g_qh[o1] = hi; *(uint32_t*)&g_ql[o1] = lo;
            } else if (col < 128) {
                split2(v00, v01, hi, lo);
                *(uint32_t*)&g_kh[o0] = hi; *(uint32_t*)&g_kl[o0] = lo;
                split2(v10, v11, hi, lo);
                *(uint32_t*)&g_kh[o1] = hi; *(uint32_t*)&g_kl[o1] = lo;
            } else {
                split2(v00, v01, hi, lo);
                *(uint32_t*)&g_vh[o0] = hi; *(uint32_t*)&g_vl[o0] = lo;
                split2(v10, v11, hi, lo);
                *(uint32_t*)&g_vh[o1] = hi; *(uint32_t*)&g_vl[o1] = lo;
            }
        }
    }
}

// ===========================================================================
// Kernel 2: flash-attention work units on mma.sync bf16.
// Unit = (batch, qtile of 64 rows, kv-chunk of up to 4x64). 4 warps, each
// owns 16 q rows. V consumed in natural [t][h] layout via ldmatrix.trans.
// ===========================================================================
#define ROWB   144
#define QH_OFF 0
#define QL_OFF 9216
#define STG_OFF 18432
#define STG_SZ  36864                       // Kh | Kl | Vh | Vl (9216 each)
#define ATTN_SMEM (STG_OFF + 2 * STG_SZ)    // 92160

__global__ __launch_bounds__(128) void attn_mma_kernel()
{
    extern __shared__ char smem[];
    const uint32_t sb = smem_to_u32(smem);
    const int tid  = threadIdx.x;
    const int w    = tid >> 5;
    const int lane = tid & 31;
    const int b    = blockIdx.y;

    // map blockIdx.x -> (qt, chunk), heavy qtiles first
    int u = blockIdx.x, qt = QT_N - 1, chunk = 0;
    for (;;) {
        int nc = (qt + 4) >> 2;
        if (u < nc) { chunk = u; break; }
        u -= nc; qt--;
    }
    const int nsub = min(4, (qt + 1) - chunk * 4);
    const int sub0 = chunk * 4;
    const int q0   = qt * 64;

    // ---- stage Q (hi+lo) ----
    {
        const __nv_bfloat16* qhp = g_qh + ((size_t)(b * Tseq + q0)) * Hdim;
        const __nv_bfloat16* qlp = g_ql + ((size_t)(b * Tseq + q0)) * Hdim;
        #pragma unroll
        for (int t = 0; t < 4; t++) {
            int seg = tid + t * 128;
            int r = seg >> 3, o = seg & 7;
            CP_ASYNC16(sb + QH_OFF + r * ROWB + o * 16, qhp + r * 64 + o * 8);
            CP_ASYNC16(sb + QL_OFF + r * ROWB + o * 16, qlp + r * 64 + o * 8);
        }
        CP_COMMIT();
    }

    auto stage = [&](int s, int buf) {
        const uint32_t o = sb + STG_OFF + (uint32_t)buf * STG_SZ;
        const size_t gbase = ((size_t)(b * Tseq + s * 64)) * Hdim;
        #pragma unroll
        for (int t = 0; t < 4; t++) {
            int seg = tid + t * 128;
            int r = seg >> 3, c = seg & 7;
            size_t ge = gbase + r * 64 + c * 8;
            CP_ASYNC16(o + r * ROWB + c * 16,         &g_kh[ge]);
            CP_ASYNC16(o + 9216 + r * ROWB + c * 16,  &g_kl[ge]);
            CP_ASYNC16(o + 18432 + r * ROWB + c * 16, &g_vh[ge]);
            CP_ASYNC16(o + 27648 + r * ROWB + c * 16, &g_vl[ge]);
        }
        CP_COMMIT();
    };

    stage(sub0, 0);
    if (nsub > 1) stage(sub0 + 1, 1);

    const int rsel  = lane & 15;
    const int ksel2 = (lane < 16) ? 0 : 16;
    // trans-ldmatrix lane map for V [kv][h]
    const int vkv  = ((lane >> 4) & 1) * 8 + (lane & 7);
    const int vh16 = ((lane >> 3) & 1) * 16;

    if (nsub > 1) { CP_WAIT(1); } else { CP_WAIT(0); }
    __syncthreads();

    uint32_t qfh[4][4], qfl[4][4];
    #pragma unroll
    for (int ks = 0; ks < 4; ks++) {
        uint32_t ro = sb + (uint32_t)(w * 16 + rsel) * ROWB + ks * 32 + ksel2;
        LDMATRIX_X4(qfh[ks][0], qfh[ks][1], qfh[ks][2], qfh[ks][3], ro + QH_OFF);
        LDMATRIX_X4(qfl[ks][0], qfl[ks][1], qfl[ks][2], qfl[ks][3], ro + QL_OFF);
    }

    float m0 = -1e30f, m1 = -1e30f, l0 = 0.f, l1 = 0.f;
    float O[8][4];
    #pragma unroll
    for (int f = 0; f < 8; f++)
        #pragma unroll
        for (int r = 0; r < 4; r++) O[f][r] = 0.f;

    const int gr  = lane >> 2;
    const int gc2 = (lane & 3) * 2;

    for (int i = 0; i < nsub; i++) {
        if (i > 0) {
            if (i + 1 < nsub) CP_WAIT(1); else CP_WAIT(0);
            __syncthreads();
        }
        const uint32_t kb = sb + STG_OFF + (uint32_t)(i & 1) * STG_SZ;
        const int sglob = sub0 + i;

        // ---- S = Q K^T (3-way split) ----
        float S[8][4];
        #pragma unroll
        for (int f = 0; f < 8; f++)
            #pragma unroll
            for (int r = 0; r < 4; r++) S[f][r] = 0.f;

        #pragma unroll
        for (int ks = 0; ks < 4; ks++) {
            #pragma unroll
            for (int nt = 0; nt < 4; nt++) {
                uint32_t ro = kb + (uint32_t)(nt * 16 + rsel) * ROWB + ks * 32 + ksel2;
                uint32_t bh[4], bl[4];
                LDMATRIX_X4(bh[0], bh[1], bh[2], bh[3], ro);
                LDMATRIX_X4(bl[0], bl[1], bl[2], bl[3], ro + 9216);
                #pragma unroll
                for (int h = 0; h < 2; h++) {
                    MMA_BF16(S[nt * 2 + h], qfh[ks], bh[h], bh[h + 2]);
                    MMA_BF16(S[nt * 2 + h], qfh[ks], bl[h], bl[h + 2]);
                    MMA_BF16(S[nt * 2 + h], qfl[ks], bh[h], bh[h + 2]);
                }
            }
        }

        // ---- causal mask (diagonal subtile only) ----
        if (sglob == qt) {
            const int r0 = q0 + w * 16 + gr;
            #pragma unroll
            for (int f = 0; f < 8; f++) {
                const int c = q0 + f * 8 + gc2;
                if (c     > r0)     S[f][0] = -1e30f;
                if (c + 1 > r0)     S[f][1] = -1e30f;
                if (c     > r0 + 8) S[f][2] = -1e30f;
                if (c + 1 > r0 + 8) S[f][3] = -1e30f;
            }
        }

        // ---- online softmax ----
        float mx0 = -1e30f, mx1 = -1e30f;
        #pragma unroll
        for (int f = 0; f < 8; f++) {
            mx0 = fmaxf(mx0, fmaxf(S[f][0], S[f][1]));
            mx1 = fmaxf(mx1, fmaxf(S[f][2], S[f][3]));
        }
        mx0 = fmaxf(mx0, __shfl_xor_sync(0xffffffffu, mx0, 1));
        mx0 = fmaxf(mx0, __shfl_xor_sync(0xffffffffu, mx0, 2));
        mx1 = fmaxf(mx1, __shfl_xor_sync(0xffffffffu, mx1, 1));
        mx1 = fmaxf(mx1, __shfl_xor_sync(0xffffffffu, mx1, 2));
        const float mn0 = fmaxf(m0, mx0), mn1 = fmaxf(m1, mx1);
        const float a0 = __expf(m0 - mn0), a1 = __expf(m1 - mn1);
        float s0 = 0.f, s1 = 0.f;
        #pragma unroll
        for (int f = 0; f < 8; f++) {
            S[f][0] = __expf(S[f][0] - mn0);
            S[f][1] = __expf(S[f][1] - mn0);
            S[f][2] = __expf(S[f][2] - mn1);
            S[f][3] = __expf(S[f][3] - mn1);
            s0 += S[f][0] + S[f][1];
            s1 += S[f][2] + S[f][3];
        }
        s0 += __shfl_xor_sync(0xffffffffu, s0, 1);
        s0 += __shfl_xor_sync(0xffffffffu, s0, 2);
        s1 += __shfl_xor_sync(0xffffffffu, s1, 1);
        s1 += __shfl_xor_sync(0xffffffffu, s1, 2);
        l0 = l0 * a0 + s0;
        l1 = l1 * a1 + s1;
        m0 = mn0; m1 = mn1;
        #pragma unroll
        for (int f = 0; f < 8; f++) {
            O[f][0] *= a0; O[f][1] *= a0;
            O[f][2] *= a1; O[f][3] *= a1;
        }

        // ---- O += P V (3-way split); V B-frags via ldmatrix.trans ----
        #pragma unroll
        for (int ks = 0; ks < 4; ks++) {
            uint32_t pha[4], pla[4];
            split2(S[2 * ks][0],     S[2 * ks][1],     pha[0], pla[0]);
            split2(S[2 * ks][2],     S[2 * ks][3],     pha[1], pla[1]);
            split2(S[2 * ks + 1][0], S[2 * ks + 1][1], pha[2], pla[2]);
            split2(S[2 * ks + 1][2], S[2 * ks + 1][3], pha[3], pla[3]);
            #pragma unroll
            for (int ht = 0; ht < 4; ht++) {
                uint32_t ro = kb + 18432u + (uint32_t)(ks * 16 + vkv) * ROWB + ht * 32 + vh16;
                uint32_t vh[4], vl[4];
                LDMATRIX_X4_TRANS(vh[0], vh[1], vh[2], vh[3], ro);
                LDMATRIX_X4_TRANS(vl[0], vl[1], vl[2], vl[3], ro + 9216);
                #pragma unroll
                for (int h = 0; h < 2; h++) {
                    MMA_BF16(O[ht * 2 + h], pha, vh[h], vh[h + 2]);
                    MMA_BF16(O[ht * 2 + h], pha, vl[h], vl[h + 2]);
                    MMA_BF16(O[ht * 2 + h], pla, vh[h], vh[h + 2]);
                }
            }
        }

        __syncthreads();
        if (i + 2 < nsub) stage(sub0 + i + 2, i & 1);
    }

    // ---- epilogue: write partials ----
    {
        const size_t base = ((size_t)((b * QT_N + qt) * MAXCH + chunk)) * 4096;
        const int r0 = w * 16 + gr;
        #pragma unroll
        for (int f = 0; f < 8; f++) {
            const int h = f * 8 + gc2;
            *(float2*)&g_pO[base + (size_t)r0 * 64 + h]       = make_float2(O[f][0], O[f][1]);
            *(float2*)&g_pO[base + (size_t)(r0 + 8) * 64 + h] = make_float2(O[f][2], O[f][3]);
        }
        if ((lane & 3) == 0) {
            const size_t sbs = (size_t)((b * QT_N + qt) * MAXCH + chunk) * 64;
            g_pm[sbs + r0]     = m0;  g_pm[sbs + r0 + 8] = m1;
            g_pl[sbs + r0]     = l0;  g_pl[sbs + r0 + 8] = l1;
        }
    }
}

// ===========================================================================
// Kernel 3: combine partials -> final output
// ===========================================================================
__global__ __launch_bounds__(256) void combine_kernel(float* __restrict__ out)
{
    int idx = blockIdx.x * 256 + threadIdx.x;
    int h4  = idx & 15;
    int q   = (idx >> 4) & (Tseq - 1);
    int b   = idx >> 15;
    int qt  = q >> 6;
    int row = q & 63;
    int nc  = (qt + 4) >> 2;

    const size_t sbs = (size_t)(b * QT_N + qt) * MAXCH * 64 + row;
    float M = -1e30f;
    for (int c = 0; c < nc; c++) M = fmaxf(M, g_pm[sbs + c * 64]);
    float L = 0.f;
    float wgt[MAXCH];
    for (int c = 0; c < nc; c++) {
        wgt[c] = __expf(g_pm[sbs + c * 64] - M);
        L += g_pl[sbs + c * 64] * wgt[c];
    }
    float ox = 0.f, oy = 0.f, oz = 0.f, ow = 0.f;
    const size_t ob = (size_t)(b * QT_N + qt) * MAXCH * 4096 + (size_t)row * 64 + h4 * 4;
    for (int c = 0; c < nc; c++) {
        float4 p = *(const float4*)&g_pO[ob + (size_t)c * 4096];
        ox += wgt[c] * p.x; oy += wgt[c] * p.y;
        oz += wgt[c] * p.z; ow += wgt[c] * p.w;
    }
    const float inv = 1.0f / L;
    *(float4*)&out[((size_t)(b * Tseq + q)) * Hdim + h4 * 4] =
        make_float4(ox * inv, oy * inv, oz * inv, ow * inv);
}

// ===========================================================================
extern "C" void kernel_launch(void* const* d_in, const int* in_sizes, int n_in,
                              void* d_out, int out_size)
{
    const float* x  = (const float*)d_in[0];
    const float* wq = (const float*)d_in[1];
    const float* wk = (const float*)d_in[2];
    const float* wv = (const float*)d_in[3];
    float* out = (float*)d_out;

    cudaFuncSetAttribute(proj_mma_kernel, cudaFuncAttributeMaxDynamicSharedMemorySize,
                         PROJ_SMEM);
    cudaFuncSetAttribute(attn_mma_kernel, cudaFuncAttributeMaxDynamicSharedMemorySize,
                         ATTN_SMEM);

    pack_w_kernel<<<(192 * Cdim) / 256, 256>>>(wq, wk, wv);
    proj_mma_kernel<<<BT / 128, 256, PROJ_SMEM>>>(x);
    attn_mma_kernel<<<dim3(144, Bb), 128, ATTN_SMEM>>>();
    combine_kernel<<<(Bb * Tseq * 16) / 256, 256>>>(out);
}